// round 9
// baseline (speedup 1.0000x reference)
#include <cuda_runtime.h>
#include <cuda_bf16.h>
#include <math.h>
#include <stdint.h>

// Shape (fixed by dataset): hidden [4,2048,1024] f32 -> N=8192 rows, H=1024, K=10.
#define H_DIM 1024
#define K_KER 10
#define WARPS 8
#define THREADS 256
#define ROWS_PER_BLOCK 16
#define KQ 8                         // K split across the 8 warps
#define KRANGE (H_DIM / KQ)          // 128 columns per warp
#define KTILES (KRANGE / 16)         // 8 m16n8k16 steps per warp
#define N_PAD 16                     // centers padded 10 -> 16 (two n-tiles of 8)
#define MAX_BLOCKS 4096
#define EPS 1e-8f

__device__ float g_partials[MAX_BLOCKS];
__device__ unsigned int g_done = 0;

__device__ __forceinline__ uint32_t bf2(float lo, float hi) {
    __nv_bfloat162 b = __floats2bfloat162_rn(lo, hi);
    return *reinterpret_cast<uint32_t*>(&b);
}
// D += A(16x16,row) * B(16x8,col)  -- bf16 in, f32 accum. sm_80+ baseline (no 'a' target needed).
__device__ __forceinline__ void mma16816(float c[4], const uint32_t a[4], const uint32_t b[2]) {
    asm volatile(
        "mma.sync.aligned.m16n8k16.row.col.f32.bf16.bf16.f32 "
        "{%0,%1,%2,%3}, {%4,%5,%6,%7}, {%8,%9}, {%0,%1,%2,%3};"
        : "+f"(c[0]), "+f"(c[1]), "+f"(c[2]), "+f"(c[3])
        : "r"(a[0]), "r"(a[1]), "r"(a[2]), "r"(a[3]), "r"(b[0]), "r"(b[1]));
}
__device__ __forceinline__ float warp_sum(float v) {
    #pragma unroll
    for (int o = 16; o; o >>= 1) v += __shfl_xor_sync(0xFFFFFFFFu, v, o);
    return v;
}

__global__ __launch_bounds__(THREADS, 3)
void knife_mma_kernel(const float* __restrict__ x,
                      const float* __restrict__ centers,
                      const float* __restrict__ weights,
                      const float* __restrict__ scales,
                      int N, int nblocks, float* __restrict__ out)
{
    __shared__ float s_dot[KQ][ROWS_PER_BLOCK][N_PAD];   // 8 KB per-kq partial dots
    __shared__ float s_xsqp[KQ][ROWS_PER_BLOCK];
    __shared__ float s_dotf[ROWS_PER_BLOCK][N_PAD];
    __shared__ float s_xsqf[ROWS_PER_BLOCK];
    __shared__ float s_csq[K_KER], s_w[K_KER], s_inv2s2[K_KER];
    __shared__ unsigned int s_is_last;
    __shared__ float s_red[WARPS];

    const int tid  = threadIdx.x;
    const int wid  = tid >> 5;      // = kq
    const int lane = tid & 31;
    const int qrow = lane >> 2;     // 0..7 : fragment row / b-col
    const int qk   = (lane & 3) * 2;

    if (tid < K_KER) {
        s_w[tid] = weights[tid];
        float sv = scales[tid];
        s_inv2s2[tid] = 1.0f / (2.0f * sv * sv);
    }
    // ||c_k||^2 (f32, L2-hot): one warp per k.
    for (int k = wid; k < K_KER; k += WARPS) {
        float acc = 0.0f;
        const float4* ck = reinterpret_cast<const float4*>(centers + k * H_DIM);
        for (int i = lane; i < H_DIM / 4; i += 32) {
            float4 v = ck[i];
            acc += v.x * v.x + v.y * v.y + v.z * v.z + v.w * v.w;
        }
        acc = warp_sum(acc);
        if (lane == 0) s_csq[k] = acc;
    }

    const int kbase = wid * KRANGE;

    // ── Preload B fragments (centers) once: bfr[tile][ntile][reg], 32 regs. ──
    // b-frag (col-major): breg0 = {B[k0][n], B[k0+1][n]}, breg1 = {B[k0+8][n], ...},
    // with B[k][n] = centers[n][k].  ntile0: n = qrow (0..7, all valid);
    // ntile1: n = qrow+8 (valid only for 8,9 -> predicated zero).
    uint32_t bfr[KTILES][2][2];
    {
        const int n0 = qrow;
        const int n1 = qrow + 8;
        const bool v1 = (n1 < K_KER);
        #pragma unroll
        for (int t = 0; t < KTILES; t++) {
            int k0 = kbase + t * 16 + qk;
            float2 p0 = *reinterpret_cast<const float2*>(centers + (size_t)n0 * H_DIM + k0);
            float2 p1 = *reinterpret_cast<const float2*>(centers + (size_t)n0 * H_DIM + k0 + 8);
            bfr[t][0][0] = bf2(p0.x, p0.y);
            bfr[t][0][1] = bf2(p1.x, p1.y);
            float2 q0 = v1 ? *reinterpret_cast<const float2*>(centers + (size_t)n1 * H_DIM + k0)
                           : make_float2(0.f, 0.f);
            float2 q1 = v1 ? *reinterpret_cast<const float2*>(centers + (size_t)n1 * H_DIM + k0 + 8)
                           : make_float2(0.f, 0.f);
            bfr[t][1][0] = bf2(q0.x, q0.y);
            bfr[t][1][1] = bf2(q1.x, q1.y);
        }
    }

    // ── Mainloop: A-frags straight from gmem (float2, frag-exact layout). ──
    const int row0 = blockIdx.x * ROWS_PER_BLOCK;
    const float* xr0 = x + (size_t)min(row0 + qrow,     N - 1) * H_DIM;
    const float* xr1 = x + (size_t)min(row0 + qrow + 8, N - 1) * H_DIM;

    float c[2][4] = {{0.f, 0.f, 0.f, 0.f}, {0.f, 0.f, 0.f, 0.f}};
    float xs0 = 0.f, xs1 = 0.f;       // xsq partials for rows qrow, qrow+8 (this thread's k-cols)

    #pragma unroll
    for (int t = 0; t < KTILES; t++) {
        const int k0 = kbase + t * 16 + qk;
        float2 p0 = *reinterpret_cast<const float2*>(xr0 + k0);      // A[m][k0,k0+1]
        float2 p1 = *reinterpret_cast<const float2*>(xr1 + k0);      // A[m+8][...]
        float2 p2 = *reinterpret_cast<const float2*>(xr0 + k0 + 8);  // A[m][k0+8,+9]
        float2 p3 = *reinterpret_cast<const float2*>(xr1 + k0 + 8);

        xs0 = fmaf(p0.x, p0.x, fmaf(p0.y, p0.y, fmaf(p2.x, p2.x, fmaf(p2.y, p2.y, xs0))));
        xs1 = fmaf(p1.x, p1.x, fmaf(p1.y, p1.y, fmaf(p3.x, p3.x, fmaf(p3.y, p3.y, xs1))));

        uint32_t a[4];
        a[0] = bf2(p0.x, p0.y);
        a[1] = bf2(p1.x, p1.y);
        a[2] = bf2(p2.x, p2.y);
        a[3] = bf2(p3.x, p3.y);

        mma16816(c[0], a, bfr[t][0]);
        mma16816(c[1], a, bfr[t][1]);
    }

    // xsq: reduce over the 4 lanes of each row-quad (lanes share qrow).
    xs0 += __shfl_xor_sync(0xFFFFFFFFu, xs0, 1);
    xs0 += __shfl_xor_sync(0xFFFFFFFFu, xs0, 2);
    xs1 += __shfl_xor_sync(0xFFFFFFFFu, xs1, 1);
    xs1 += __shfl_xor_sync(0xFFFFFFFFu, xs1, 2);
    if ((lane & 3) == 0) {
        s_xsqp[wid][qrow]     = xs0;
        s_xsqp[wid][qrow + 8] = xs1;
    }

    // c-frags -> smem: c0,c1 = D[m][nb+qk, +1]; c2,c3 = D[m+8][nb+qk, +1].
    #pragma unroll
    for (int nt = 0; nt < 2; nt++) {
        int nb = nt * 8 + qk;
        *reinterpret_cast<float2*>(&s_dot[wid][qrow][nb])     = make_float2(c[nt][0], c[nt][1]);
        *reinterpret_cast<float2*>(&s_dot[wid][qrow + 8][nb]) = make_float2(c[nt][2], c[nt][3]);
    }
    __syncthreads();

    // Reduce the K-split: 256 threads cover 16x16 outputs.
    {
        int row = tid >> 4, col = tid & 15;
        float s = 0.f;
        #pragma unroll
        for (int q = 0; q < KQ; q++) s += s_dot[q][row][col];
        s_dotf[row][col] = s;
        if (col == 0) {
            float xq = 0.f;
            #pragma unroll
            for (int q = 0; q < KQ; q++) xq += s_xsqp[q][row];
            s_xsqf[row] = xq;
        }
    }
    __syncthreads();

    // Density + log per row (16 rows; lanes 0-15 of warp 0).
    float logsum = 0.0f;
    if (wid == 0) {
        if (lane < ROWS_PER_BLOCK && (row0 + lane) < N) {
            float xq = s_xsqf[lane];
            float density = 0.0f;
            #pragma unroll
            for (int k = 0; k < K_KER; k++) {
                float dsq = fmaxf(xq + s_csq[k] - 2.0f * s_dotf[lane][k], 0.0f);
                density += s_w[k] * expf(-dsq * s_inv2s2[k]);
            }
            logsum = logf(density + EPS);
        }
        logsum = warp_sum(logsum);
        if (lane == 0) g_partials[blockIdx.x] = logsum;
    }

    // ── Fused finalize: last block reduces all partials. ──
    __threadfence();
    __syncthreads();
    if (tid == 0) {
        unsigned int prev = atomicAdd(&g_done, 1u);
        s_is_last = (prev == (unsigned int)(nblocks - 1)) ? 1u : 0u;
    }
    __syncthreads();
    if (s_is_last) {
        float acc = 0.0f;
        for (int i = tid; i < nblocks; i += THREADS)
            acc += g_partials[i];
        acc = warp_sum(acc);
        if (lane == 0) s_red[wid] = acc;
        __syncthreads();
        if (tid == 0) {
            float s = 0.0f;
            #pragma unroll
            for (int w = 0; w < WARPS; w++) s += s_red[w];
            float h = -s / (float)N;          // h_entropy
            float entropy_loss = h;           // BETA = 1.0
            float target_loss  = h * h;       // TARGET_ENTROPY = 0.0
            out[0] = entropy_loss;
            out[1] = target_loss;
            out[2] = entropy_loss + target_loss;
            out[3] = h;
            g_done = 0;                       // reset for next graph replay
        }
    }
}

extern "C" void kernel_launch(void* const* d_in, const int* in_sizes, int n_in,
                              void* d_out, int out_size)
{
    const float* x       = (const float*)d_in[0];
    const float* centers = (const float*)d_in[1];
    const float* weights = (const float*)d_in[2];
    const float* scales  = (const float*)d_in[3];
    float* out = (float*)d_out;

    const int N = in_sizes[0] / H_DIM;                           // 8192
    int blocks = (N + ROWS_PER_BLOCK - 1) / ROWS_PER_BLOCK;      // 512
    if (blocks > MAX_BLOCKS) blocks = MAX_BLOCKS;

    knife_mma_kernel<<<blocks, THREADS>>>(x, centers, weights, scales, N, blocks, out);
}

// round 10
// speedup vs baseline: 1.0171x; 1.0171x over previous
#include <cuda_runtime.h>
#include <cuda_bf16.h>
#include <math.h>
#include <stdint.h>

// Shape (fixed by dataset): hidden [4,2048,1024] f32 -> N=8192 rows, H=1024, K=10.
#define H_DIM 1024
#define K_KER 10
#define WARPS 8
#define THREADS 256
#define ROWS_PER_BLOCK 16
#define KQ 8                          // K split across the 8 warps
#define KRANGE (H_DIM / KQ)           // 128 columns per warp
#define KTILES (KRANGE / 16)          // 8 m16n8k16 steps per warp
#define N_PAD 16
#define MAX_BLOCKS 4096
#define EPS 1e-8f

// Padded smem row: 1024 + 8 bf16 = 2064 B -> ldmatrix phases conflict-free.
#define ROWSTRIDE 1032

__device__ float g_partials[MAX_BLOCKS];
__device__ unsigned int g_done = 0;

__device__ __forceinline__ uint32_t bf2(float lo, float hi) {
    __nv_bfloat162 b = __floats2bfloat162_rn(lo, hi);
    return *reinterpret_cast<uint32_t*>(&b);
}
__device__ __forceinline__ void mma16816(float c[4], const uint32_t a[4], const uint32_t b[2]) {
    asm volatile(
        "mma.sync.aligned.m16n8k16.row.col.f32.bf16.bf16.f32 "
        "{%0,%1,%2,%3}, {%4,%5,%6,%7}, {%8,%9}, {%0,%1,%2,%3};"
        : "+f"(c[0]), "+f"(c[1]), "+f"(c[2]), "+f"(c[3])
        : "r"(a[0]), "r"(a[1]), "r"(a[2]), "r"(a[3]), "r"(b[0]), "r"(b[1]));
}
__device__ __forceinline__ float warp_sum(float v) {
    #pragma unroll
    for (int o = 16; o; o >>= 1) v += __shfl_xor_sync(0xFFFFFFFFu, v, o);
    return v;
}
__device__ __forceinline__ uint32_t smem_u32(const void* p) {
    uint32_t a;
    asm("{ .reg .u64 t; cvta.to.shared.u64 t, %1; cvt.u32.u64 %0, t; }" : "=r"(a) : "l"(p));
    return a;
}

__global__ __launch_bounds__(THREADS, 3)
void knife_mma_kernel(const float* __restrict__ x,
                      const float* __restrict__ centers,
                      const float* __restrict__ weights,
                      const float* __restrict__ scales,
                      int N, int nblocks, float* __restrict__ out)
{
    __shared__ __nv_bfloat16 s_x[ROWS_PER_BLOCK * ROWSTRIDE];   // ~33 KB staged tile
    __shared__ float s_dot[KQ][ROWS_PER_BLOCK][N_PAD];          // 8 KB K-split partials
    __shared__ float s_dotf[ROWS_PER_BLOCK][N_PAD];
    __shared__ float s_xsqf[ROWS_PER_BLOCK];
    __shared__ float s_csq[K_KER], s_w[K_KER], s_inv2s2[K_KER];
    __shared__ unsigned int s_is_last;
    __shared__ float s_red[WARPS];

    const int tid  = threadIdx.x;
    const int wid  = tid >> 5;
    const int lane = tid & 31;
    const int qrow = lane >> 2;       // 0..7
    const int qk   = (lane & 3) * 2;

    if (tid < K_KER) {
        s_w[tid] = weights[tid];
        float sv = scales[tid];
        s_inv2s2[tid] = 1.0f / (2.0f * sv * sv);
    }
    // ||c_k||^2 (f32, L1/L2-hot): one warp per k.
    for (int k = wid; k < K_KER; k += WARPS) {
        float acc = 0.0f;
        const float4* ck = reinterpret_cast<const float4*>(centers + k * H_DIM);
        for (int i = lane; i < H_DIM / 4; i += 32) {
            float4 v = ck[i];
            acc += v.x * v.x + v.y * v.y + v.z * v.z + v.w * v.w;
        }
        acc = warp_sum(acc);
        if (lane == 0) s_csq[k] = acc;
    }

    // ── Stage tile: warp w loads rows 2w, 2w+1 with float4-coalesced LDG,
    //    converts f32->bf16 into padded smem, folds xsq into the same pass. ──
    const int row0 = blockIdx.x * ROWS_PER_BLOCK;
    const float4* x4 = reinterpret_cast<const float4*>(x);
    float xs[2] = {0.f, 0.f};
    #pragma unroll
    for (int i = 0; i < 16; i++) {
        const int rl   = 2 * wid + (i >> 3);                 // local row
        const int col4 = (i & 7) * 32 + lane;                // float4 index in row
        const int grow = min(row0 + rl, N - 1);
        float4 v = x4[(size_t)grow * (H_DIM / 4) + col4];
        xs[i >> 3] = fmaf(v.x, v.x, fmaf(v.y, v.y, fmaf(v.z, v.z, fmaf(v.w, v.w, xs[i >> 3]))));
        __nv_bfloat162 b0 = __floats2bfloat162_rn(v.x, v.y);
        __nv_bfloat162 b1 = __floats2bfloat162_rn(v.z, v.w);
        uint2 pk = make_uint2(*reinterpret_cast<uint32_t*>(&b0), *reinterpret_cast<uint32_t*>(&b1));
        *reinterpret_cast<uint2*>(&s_x[rl * ROWSTRIDE + col4 * 4]) = pk;
    }
    xs[0] = warp_sum(xs[0]);
    xs[1] = warp_sum(xs[1]);
    if (lane == 0) { s_xsqf[2 * wid] = xs[0]; s_xsqf[2 * wid + 1] = xs[1]; }
    __syncthreads();

    // ── Compute: warp w covers K columns [w*128, w*128+128). A from ldmatrix,
    //    B per-tile from gmem (40 KB centers -> L1-resident). ──
    const int kbase = wid * KRANGE;
    const int n0 = qrow;
    const int n1 = qrow + 8;
    const bool v1 = (n1 < K_KER);
    float c[2][4] = {{0.f, 0.f, 0.f, 0.f}, {0.f, 0.f, 0.f, 0.f}};

    #pragma unroll
    for (int t = 0; t < KTILES; t++) {
        const int k0 = kbase + t * 16;
        // A-frag: lanes 0-15 -> rows, lanes 16-31 -> +8 column chunk.
        uint32_t a[4];
        uint32_t addr = smem_u32(&s_x[(lane & 15) * ROWSTRIDE + k0 + ((lane >> 4) << 3)]);
        asm volatile("ldmatrix.sync.aligned.m8n8.x4.shared.b16 {%0,%1,%2,%3}, [%4];"
                     : "=r"(a[0]), "=r"(a[1]), "=r"(a[2]), "=r"(a[3]) : "r"(addr));
        // B-frags (col-major): b0 = centers[n][k0+qk, +1], b1 = +8.
        uint32_t b0[2], b1[2];
        {
            float2 p0 = *reinterpret_cast<const float2*>(centers + (size_t)n0 * H_DIM + k0 + qk);
            float2 p1 = *reinterpret_cast<const float2*>(centers + (size_t)n0 * H_DIM + k0 + qk + 8);
            b0[0] = bf2(p0.x, p0.y);
            b0[1] = bf2(p1.x, p1.y);
            float2 q0 = v1 ? *reinterpret_cast<const float2*>(centers + (size_t)n1 * H_DIM + k0 + qk)
                           : make_float2(0.f, 0.f);
            float2 q1 = v1 ? *reinterpret_cast<const float2*>(centers + (size_t)n1 * H_DIM + k0 + qk + 8)
                           : make_float2(0.f, 0.f);
            b1[0] = bf2(q0.x, q0.y);
            b1[1] = bf2(q1.x, q1.y);
        }
        mma16816(c[0], a, b0);
        mma16816(c[1], a, b1);
    }

    // c-frags -> smem: c0,c1 = D[qrow][nb+qk,+1]; c2,c3 = D[qrow+8][...].
    #pragma unroll
    for (int nt = 0; nt < 2; nt++) {
        int nb = nt * 8 + qk;
        *reinterpret_cast<float2*>(&s_dot[wid][qrow][nb])     = make_float2(c[nt][0], c[nt][1]);
        *reinterpret_cast<float2*>(&s_dot[wid][qrow + 8][nb]) = make_float2(c[nt][2], c[nt][3]);
    }
    __syncthreads();

    // Reduce the K-split: 256 threads cover 16x16 outputs.
    {
        int row = tid >> 4, col = tid & 15;
        float s = 0.f;
        #pragma unroll
        for (int q = 0; q < KQ; q++) s += s_dot[q][row][col];
        s_dotf[row][col] = s;
    }
    __syncthreads();

    // Density + log per row (lanes 0-15 of warp 0).
    if (wid == 0) {
        float logsum = 0.0f;
        if (lane < ROWS_PER_BLOCK && (row0 + lane) < N) {
            float xq = s_xsqf[lane];
            float density = 0.0f;
            #pragma unroll
            for (int k = 0; k < K_KER; k++) {
                float dsq = fmaxf(xq + s_csq[k] - 2.0f * s_dotf[lane][k], 0.0f);
                density += s_w[k] * expf(-dsq * s_inv2s2[k]);
            }
            logsum = logf(density + EPS);
        }
        logsum = warp_sum(logsum);
        if (lane == 0) g_partials[blockIdx.x] = logsum;
    }

    // ── Fused finalize: last block reduces all partials. ──
    __threadfence();
    __syncthreads();
    if (tid == 0) {
        unsigned int prev = atomicAdd(&g_done, 1u);
        s_is_last = (prev == (unsigned int)(nblocks - 1)) ? 1u : 0u;
    }
    __syncthreads();
    if (s_is_last) {
        float acc = 0.0f;
        for (int i = tid; i < nblocks; i += THREADS)
            acc += g_partials[i];
        acc = warp_sum(acc);
        if (lane == 0) s_red[wid] = acc;
        __syncthreads();
        if (tid == 0) {
            float s = 0.0f;
            #pragma unroll
            for (int w = 0; w < WARPS; w++) s += s_red[w];
            float h = -s / (float)N;          // h_entropy
            float entropy_loss = h;           // BETA = 1.0
            float target_loss  = h * h;       // TARGET_ENTROPY = 0.0
            out[0] = entropy_loss;
            out[1] = target_loss;
            out[2] = entropy_loss + target_loss;
            out[3] = h;
            g_done = 0;                       // reset for next graph replay
        }
    }
}

extern "C" void kernel_launch(void* const* d_in, const int* in_sizes, int n_in,
                              void* d_out, int out_size)
{
    const float* x       = (const float*)d_in[0];
    const float* centers = (const float*)d_in[1];
    const float* weights = (const float*)d_in[2];
    const float* scales  = (const float*)d_in[3];
    float* out = (float*)d_out;

    const int N = in_sizes[0] / H_DIM;                           // 8192
    int blocks = (N + ROWS_PER_BLOCK - 1) / ROWS_PER_BLOCK;      // 512
    if (blocks > MAX_BLOCKS) blocks = MAX_BLOCKS;

    knife_mma_kernel<<<blocks, THREADS>>>(x, centers, weights, scales, N, blocks, out);
}